// round 1
// baseline (speedup 1.0000x reference)
#include <cuda_runtime.h>
#include <math.h>

#define NQ   2048
#define MREF 50000
#define DD   128
#define NPAD 50048              // 391 * 128, padded ref count
#define KMAX 16                 // per-thread top-list capacity (k+1 = 11 <= 16)

// ---------------- device scratch (static, allocation-free) ----------------
__device__ float g_zn[NQ * DD];                       // normalized queries   (1 MB)
__device__ float g_rn[NPAD * DD];                     // normalized refs, zero-padded (25.6 MB)
__device__ float g_dots[(size_t)NQ * NPAD];           // all dot products     (410 MB)

// ---------------- 1) row L2-normalization ----------------
// one block (128 threads) per row; which==0 -> g_zn, which!=0 -> g_rn
__global__ void normalize_rows(const float* __restrict__ in, int rows, int which) {
    int r = blockIdx.x;
    if (r >= rows) return;
    int t = threadIdx.x;                    // 0..127
    float v = in[r * DD + t];
    float s = v * v;
    #pragma unroll
    for (int o = 16; o > 0; o >>= 1) s += __shfl_down_sync(0xffffffffu, s, o);
    __shared__ float ws[4];
    if ((t & 31) == 0) ws[t >> 5] = s;
    __syncthreads();
    float tot = ws[0] + ws[1] + ws[2] + ws[3];
    float inv = rsqrtf(tot);
    float* out = which ? g_rn : g_zn;
    out[r * DD + t] = v * inv;
}

// ---------------- 2) fp32 SIMT GEMM: g_dots = g_zn * g_rn^T ----------------
// 128x128 tile, BK=16, 256 threads, 8x8 per-thread microtile
__global__ void __launch_bounds__(256, 2) sgemm_dots() {
    __shared__ __align__(16) float As[16][128];
    __shared__ __align__(16) float Bs[16][128];

    const int tid  = threadIdx.x;
    const int m0   = blockIdx.y * 128;      // query tile
    const int n0   = blockIdx.x * 128;      // ref tile
    const int lrow = tid >> 2;              // 0..63
    const int lcol = (tid & 3) * 4;         // 0,4,8,12
    const int tx   = tid & 15;
    const int ty   = tid >> 4;

    float acc[8][8];
    #pragma unroll
    for (int i = 0; i < 8; i++)
        #pragma unroll
        for (int j = 0; j < 8; j++) acc[i][j] = 0.0f;

    for (int k0 = 0; k0 < DD; k0 += 16) {
        #pragma unroll
        for (int rr = 0; rr < 2; rr++) {
            int row = lrow + rr * 64;
            float4 a = *(const float4*)&g_zn[(m0 + row) * DD + k0 + lcol];
            As[lcol + 0][row] = a.x; As[lcol + 1][row] = a.y;
            As[lcol + 2][row] = a.z; As[lcol + 3][row] = a.w;
            float4 b = *(const float4*)&g_rn[(n0 + row) * DD + k0 + lcol];
            Bs[lcol + 0][row] = b.x; Bs[lcol + 1][row] = b.y;
            Bs[lcol + 2][row] = b.z; Bs[lcol + 3][row] = b.w;
        }
        __syncthreads();

        #pragma unroll
        for (int kk = 0; kk < 16; kk++) {
            float ar[8], br[8];
            *(float4*)&ar[0] = *(const float4*)&As[kk][ty * 8 + 0];
            *(float4*)&ar[4] = *(const float4*)&As[kk][ty * 8 + 4];
            *(float4*)&br[0] = *(const float4*)&Bs[kk][tx * 8 + 0];
            *(float4*)&br[4] = *(const float4*)&Bs[kk][tx * 8 + 4];
            #pragma unroll
            for (int i = 0; i < 8; i++)
                #pragma unroll
                for (int j = 0; j < 8; j++)
                    acc[i][j] += ar[i] * br[j];
        }
        __syncthreads();
    }

    #pragma unroll
    for (int i = 0; i < 8; i++) {
        size_t base = (size_t)(m0 + ty * 8 + i) * NPAD + n0 + tx * 8;
        float4 v0 = make_float4(acc[i][0], acc[i][1], acc[i][2], acc[i][3]);
        float4 v1 = make_float4(acc[i][4], acc[i][5], acc[i][6], acc[i][7]);
        *(float4*)&g_dots[base + 0] = v0;
        *(float4*)&g_dots[base + 4] = v1;
    }
}

// ---------------- 3) per-query (k+1)-th largest dot -> distance ----------------
// one block (256 threads) per query
__global__ void select_kth(const int* __restrict__ kptr, float* __restrict__ out) {
    const int q  = blockIdx.x;
    const int t  = threadIdx.x;
    const int kk = kptr[0] + 1;                     // k-th index (0-based) => (k+1)-th largest

    // per-thread top-KMAX (descending; top[KMAX-1] is the current min)
    float top[KMAX];
    #pragma unroll
    for (int i = 0; i < KMAX; i++) top[i] = -1e30f;

    const float* row = g_dots + (size_t)q * NPAD;
    for (int m = t; m < MREF; m += 256) {
        float v = __ldg(&row[m]);
        if (v > top[KMAX - 1]) {
            top[KMAX - 1] = v;
            #pragma unroll
            for (int i = KMAX - 1; i > 0; i--) {
                if (top[i] > top[i - 1]) { float tmp = top[i - 1]; top[i - 1] = top[i]; top[i] = tmp; }
            }
        }
    }

    __shared__ float cand[256 * KMAX];
    __shared__ float rv[256];
    __shared__ int   ri[256];
    #pragma unroll
    for (int i = 0; i < KMAX; i++) cand[t * KMAX + i] = top[i];
    __syncthreads();

    float kth = -1e30f;
    for (int it = 0; it < kk; it++) {
        float lm = -1e30f; int li = t * KMAX;
        #pragma unroll
        for (int i = 0; i < KMAX; i++) {
            float v = cand[t * KMAX + i];
            if (v > lm) { lm = v; li = t * KMAX + i; }
        }
        rv[t] = lm; ri[t] = li;
        __syncthreads();
        for (int s = 128; s > 0; s >>= 1) {
            if (t < s && rv[t + s] > rv[t]) { rv[t] = rv[t + s]; ri[t] = ri[t + s]; }
            __syncthreads();
        }
        kth = rv[0];                     // global max this round
        if (t == 0) cand[ri[0]] = -1e30f;
        __syncthreads();
    }

    if (t == 0) {
        float sq = 2.0f - 2.0f * kth;
        out[q] = sqrtf(fmaxf(sq, 1e-12f));
    }
}

// ---------------- launch ----------------
extern "C" void kernel_launch(void* const* d_in, const int* in_sizes, int n_in,
                              void* d_out, int out_size) {
    const float* z    = (const float*)d_in[0];   // [2048,128] fp32
    const float* ref  = (const float*)d_in[1];   // [50000,128] fp32
    const int*   kptr = (const int*)d_in[2];     // scalar k
    float*       out  = (float*)d_out;           // [2048] fp32

    normalize_rows<<<NQ,   128>>>(z,   NQ,   0);
    normalize_rows<<<MREF, 128>>>(ref, MREF, 1);

    dim3 grid(NPAD / 128, NQ / 128);             // (391, 16)
    sgemm_dots<<<grid, 256>>>();

    select_kth<<<NQ, 256>>>(kptr, out);
}

// round 5
// speedup vs baseline: 1.0476x; 1.0476x over previous
#include <cuda_runtime.h>
#include <cuda_fp16.h>
#include <stdint.h>
#include <math.h>

#define NQ     2048
#define MREF   50000
#define DD     128
#define NPAD   50048              // 391 * 128
#define NTILES 391
#define CHUNK  32
#define NCHUNK (NPAD / CHUNK)     // 1564
#define S      136                // padded smem row stride in halfs (272 B)

// ---------------- static device scratch (allocation-free) ----------------
__device__ __align__(16) __half g_a[NQ * DD];             // normalized queries, fp16
__device__ __align__(16) __half g_b[NPAD * DD];           // normalized refs, zero-padded
__device__ float g_dotsT[(size_t)NPAD * NQ];              // column-major dots (410 MB)
__device__ float g_gmax[(size_t)NCHUNK * NQ];             // per-(32-col chunk, query) max

__device__ __forceinline__ uint32_t smem_u32(const void* p) {
    uint32_t a;
    asm("{ .reg .u64 t; cvta.to.shared.u64 t, %1; cvt.u32.u64 %0, t; }" : "=r"(a) : "l"(p));
    return a;
}

// ---------------- 1) normalize rows -> fp16 ----------------
__global__ void normalize_rows(const float* __restrict__ in, int rows, int which) {
    int r = blockIdx.x;
    if (r >= rows) return;
    int t = threadIdx.x;                 // 0..127
    float v = in[r * DD + t];
    float s = v * v;
    #pragma unroll
    for (int o = 16; o > 0; o >>= 1) s += __shfl_xor_sync(0xffffffffu, s, o);
    __shared__ float ws[4];
    if ((t & 31) == 0) ws[t >> 5] = s;
    __syncthreads();
    float inv = rsqrtf(ws[0] + ws[1] + ws[2] + ws[3]);
    __half h = __float2half(v * inv);
    if (which) g_b[r * DD + t] = h;
    else       g_a[r * DD + t] = h;
}

// ---------------- 2) HMMA GEMM (mma.sync m16n8k16 fp16->fp32) ----------------
// grid (391, 16), 256 threads (8 warps, 2x4 warp grid), warp tile 64x32, K=128 resident
__global__ void __launch_bounds__(256, 2) knn_gemm() {
    extern __shared__ __align__(16) __half sm[];
    __half* Asm = sm;                    // [128][S]
    __half* Bsm = sm + 128 * S;          // [128][S]

    const int tid  = threadIdx.x;
    const int wid  = tid >> 5, lane = tid & 31;
    const int n0   = blockIdx.x * 128, m0 = blockIdx.y * 128;
    const int wm   = wid & 1;            // 0..1 (M)
    const int wn   = wid >> 1;           // 0..3 (N)

    // ---- cooperative gmem -> smem (coalesced 16B, padded rows) ----
    {
        const uint4* a = (const uint4*)(g_a + (size_t)m0 * DD);
        const uint4* b = (const uint4*)(g_b + (size_t)n0 * DD);
        #pragma unroll
        for (int it = 0; it < 8; it++) {
            int c = tid + it * 256;          // 0..2047
            int r = c >> 4, q = c & 15;      // row, 8-half chunk
            *(uint4*)&Asm[r * S + q * 8] = a[c];
            *(uint4*)&Bsm[r * S + q * 8] = b[c];
        }
    }
    __syncthreads();

    float acc[4][4][4];
    #pragma unroll
    for (int i = 0; i < 4; i++)
        #pragma unroll
        for (int j = 0; j < 4; j++)
            #pragma unroll
            for (int x = 0; x < 4; x++) acc[i][j][x] = 0.0f;

    const uint32_t a_base = smem_u32(Asm);
    const uint32_t b_base = smem_u32(Bsm);
    // ldmatrix x4 lane-address bases (rows = lane&15, col half-offset = (lane>>4)*8)
    const uint32_t aoff = ((uint32_t)((wm * 64 + (lane & 15)) * S + (lane >> 4) * 8)) * 2;
    const uint32_t boff = ((uint32_t)((wn * 32 + (lane & 15)) * S + (lane >> 4) * 8)) * 2;

    #pragma unroll
    for (int ks = 0; ks < 8; ks++) {
        const uint32_t kb = (uint32_t)(ks * 16) * 2;   // byte offset along K
        uint32_t af[4][4];
        #pragma unroll
        for (int mi = 0; mi < 4; mi++) {
            uint32_t addr = a_base + aoff + (uint32_t)(mi * 16 * S) * 2 + kb;
            asm volatile("ldmatrix.sync.aligned.m8n8.x4.shared.b16 {%0,%1,%2,%3}, [%4];"
                         : "=r"(af[mi][0]), "=r"(af[mi][1]), "=r"(af[mi][2]), "=r"(af[mi][3])
                         : "r"(addr));
        }
        uint32_t bf[2][4];
        #pragma unroll
        for (int np = 0; np < 2; np++) {
            uint32_t addr = b_base + boff + (uint32_t)(np * 16 * S) * 2 + kb;
            asm volatile("ldmatrix.sync.aligned.m8n8.x4.shared.b16 {%0,%1,%2,%3}, [%4];"
                         : "=r"(bf[np][0]), "=r"(bf[np][1]), "=r"(bf[np][2]), "=r"(bf[np][3])
                         : "r"(addr));
        }
        #pragma unroll
        for (int mi = 0; mi < 4; mi++) {
            #pragma unroll
            for (int ni = 0; ni < 4; ni++) {
                // n-tile ni: pair np = ni>>1, sub = ni&1 -> b regs {sub, sub+2}
                uint32_t b0 = bf[ni >> 1][ni & 1];
                uint32_t b1 = bf[ni >> 1][(ni & 1) + 2];
                asm volatile(
                    "mma.sync.aligned.m16n8k16.row.col.f32.f16.f16.f32 "
                    "{%0,%1,%2,%3}, {%4,%5,%6,%7}, {%8,%9}, {%0,%1,%2,%3};"
                    : "+f"(acc[mi][ni][0]), "+f"(acc[mi][ni][1]),
                      "+f"(acc[mi][ni][2]), "+f"(acc[mi][ni][3])
                    : "r"(af[mi][0]), "r"(af[mi][1]), "r"(af[mi][2]), "r"(af[mi][3]),
                      "r"(b0), "r"(b1));
            }
        }
    }

    // ---- epilogue: store dots col-major + fused per-row 32-col max ----
    const int g  = lane >> 2;            // acc row group
    const int tc = (lane & 3) * 2;       // acc col pair
    const bool tail = (blockIdx.x == NTILES - 1);
    const int chunk = (n0 >> 5) + wn;    // this warp's 32-col chunk id

    #pragma unroll
    for (int mi = 0; mi < 4; mi++) {
        const int r1 = m0 + wm * 64 + mi * 16 + g;       // rows r1, r1+8
        float mx0 = -3.0e38f, mx1 = -3.0e38f;
        #pragma unroll
        for (int ni = 0; ni < 4; ni++) {
            const int col = n0 + wn * 32 + ni * 8 + tc;
            float v0 = acc[mi][ni][0], v1 = acc[mi][ni][1];
            float w0 = acc[mi][ni][2], w1 = acc[mi][ni][3];
            if (tail) {
                if (col     >= MREF) { v0 = -3.0e38f; w0 = -3.0e38f; }
                if (col + 1 >= MREF) { v1 = -3.0e38f; w1 = -3.0e38f; }
            }
            g_dotsT[(size_t) col      * NQ + r1    ] = v0;
            g_dotsT[(size_t)(col + 1) * NQ + r1    ] = v1;
            g_dotsT[(size_t) col      * NQ + r1 + 8] = w0;
            g_dotsT[(size_t)(col + 1) * NQ + r1 + 8] = w1;
            mx0 = fmaxf(mx0, fmaxf(v0, v1));
            mx1 = fmaxf(mx1, fmaxf(w0, w1));
        }
        mx0 = fmaxf(mx0, __shfl_xor_sync(0xffffffffu, mx0, 1));
        mx0 = fmaxf(mx0, __shfl_xor_sync(0xffffffffu, mx0, 2));
        mx1 = fmaxf(mx1, __shfl_xor_sync(0xffffffffu, mx1, 1));
        mx1 = fmaxf(mx1, __shfl_xor_sync(0xffffffffu, mx1, 2));
        if ((lane & 3) == 0) {
            g_gmax[(size_t)chunk * NQ + r1    ] = mx0;
            g_gmax[(size_t)chunk * NQ + r1 + 8] = mx1;
        }
    }
}

// ---------------- 3) chunk-max guided exact selection (1 thread / query) ----------------
__device__ __forceinline__ void insert_desc(float* top, float v) {
    top[15] = v;
    #pragma unroll
    for (int i = 15; i > 0; i--) {
        if (top[i] > top[i - 1]) { float t = top[i - 1]; top[i - 1] = top[i]; top[i] = t; }
    }
}

__global__ void phase2_select(const int* __restrict__ kptr, float* __restrict__ out) {
    int q = blockIdx.x * 32 + threadIdx.x;
    if (q >= NQ) return;
    int kk = kptr[0] + 1;
    kk = kk < 1 ? 1 : (kk > 16 ? 16 : kk);

    float top[16];
    #pragma unroll
    for (int i = 0; i < 16; i++) top[i] = -3.0e38f;

    float hi_bound = 3.4e38f;
    bool done = false;

    for (int outer = 0; outer < 8 && !done; outer++) {
        // top-16 chunk maxima strictly below hi_bound
        float cv[16]; int ci[16];
        #pragma unroll
        for (int i = 0; i < 16; i++) { cv[i] = -3.0e38f; ci[i] = -1; }
        for (int c = 0; c < NCHUNK; c++) {
            float m = g_gmax[(size_t)c * NQ + q];
            if (m < hi_bound && m > cv[15]) {
                cv[15] = m; ci[15] = c;
                #pragma unroll
                for (int i = 15; i > 0; i--) {
                    if (cv[i] > cv[i - 1]) {
                        float tv = cv[i - 1]; cv[i - 1] = cv[i]; cv[i] = tv;
                        int   ti = ci[i - 1]; ci[i - 1] = ci[i]; ci[i] = ti;
                    }
                }
            }
        }
        if (ci[0] < 0) { done = true; break; }
        for (int t = 0; t < 16; t++) {
            if (ci[t] < 0 || cv[t] <= top[kk - 1]) { done = true; break; }
            const float* base = g_dotsT + (size_t)ci[t] * CHUNK * NQ + q;
            #pragma unroll 8
            for (int j = 0; j < CHUNK; j++) {
                float v = base[(size_t)j * NQ];
                if (v > top[kk - 1]) insert_desc(top, v);
            }
        }
        hi_bound = cv[15];
        if (!done && hi_bound <= top[kk - 1]) done = true;
    }

    if (!done) {   // exhaustive fallback (pathological ties only)
        for (int c = 0; c < NCHUNK; c++) {
            if (g_gmax[(size_t)c * NQ + q] > top[kk - 1]) {
                const float* base = g_dotsT + (size_t)c * CHUNK * NQ + q;
                for (int j = 0; j < CHUNK; j++) {
                    float v = base[(size_t)j * NQ];
                    if (v > top[kk - 1]) insert_desc(top, v);
                }
            }
        }
    }

    float kth = top[kk - 1];
    out[q] = sqrtf(fmaxf(2.0f - 2.0f * kth, 1e-12f));
}

// ---------------- launch ----------------
extern "C" void kernel_launch(void* const* d_in, const int* in_sizes, int n_in,
                              void* d_out, int out_size) {
    const float* z    = (const float*)d_in[0];   // [2048,128]
    const float* ref  = (const float*)d_in[1];   // [50000,128]
    const int*   kptr = (const int*)d_in[2];     // scalar k
    float*       out  = (float*)d_out;           // [2048]

    const int smem_bytes = 2 * 128 * S * (int)sizeof(__half);   // 69632
    cudaFuncSetAttribute(knn_gemm, cudaFuncAttributeMaxDynamicSharedMemorySize, smem_bytes);

    normalize_rows<<<NQ,   128>>>(z,   NQ,   0);
    normalize_rows<<<MREF, 128>>>(ref, MREF, 1);

    dim3 grid(NTILES, 16);
    knn_gemm<<<grid, 256, smem_bytes>>>();

    phase2_select<<<NQ / 32, 32>>>(kptr, out);
}

// round 6
// speedup vs baseline: 2.6420x; 2.5221x over previous
#include <cuda_runtime.h>
#include <cuda_fp16.h>
#include <stdint.h>
#include <math.h>

#define NQ     2048
#define MREF   50000
#define DD     128
#define NPAD   50048              // 391 * 128
#define NTILES 391
#define CHUNK  32
#define NCHUNK (NPAD / CHUNK)     // 1564
#define S      136                // padded smem row stride in halfs (272 B)
#define CANDMAX 4096

// ---------------- static device scratch (allocation-free) ----------------
__device__ __align__(16) __half g_a[NQ * DD];             // normalized queries, fp16
__device__ __align__(16) __half g_b[NPAD * DD];           // normalized refs, zero-padded
__device__ float g_dotsT[(size_t)NPAD * NQ];              // column-major dots (410 MB)
__device__ float g_gmax[(size_t)NCHUNK * NQ];             // per-(32-col chunk, query) max

__device__ __forceinline__ uint32_t smem_u32(const void* p) {
    uint32_t a;
    asm("{ .reg .u64 t; cvta.to.shared.u64 t, %1; cvt.u32.u64 %0, t; }" : "=r"(a) : "l"(p));
    return a;
}

// ---------------- 1) normalize rows -> fp16 ----------------
__global__ void normalize_rows(const float* __restrict__ in, int rows, int which) {
    int r = blockIdx.x;
    if (r >= rows) return;
    int t = threadIdx.x;                 // 0..127
    float v = in[r * DD + t];
    float s = v * v;
    #pragma unroll
    for (int o = 16; o > 0; o >>= 1) s += __shfl_xor_sync(0xffffffffu, s, o);
    __shared__ float ws[4];
    if ((t & 31) == 0) ws[t >> 5] = s;
    __syncthreads();
    float inv = rsqrtf(ws[0] + ws[1] + ws[2] + ws[3]);
    __half h = __float2half(v * inv);
    if (which) g_b[r * DD + t] = h;
    else       g_a[r * DD + t] = h;
}

// ---------------- 2) HMMA GEMM (mma.sync m16n8k16 fp16->fp32) ----------------
// grid (391, 16), 256 threads (8 warps, 2x4 warp grid), warp tile 64x32, K=128 resident
__global__ void __launch_bounds__(256, 2) knn_gemm() {
    extern __shared__ __align__(16) __half sm[];
    __half* Asm = sm;                    // [128][S]
    __half* Bsm = sm + 128 * S;          // [128][S]

    const int tid  = threadIdx.x;
    const int wid  = tid >> 5, lane = tid & 31;
    const int n0   = blockIdx.x * 128, m0 = blockIdx.y * 128;
    const int wm   = wid & 1;            // 0..1 (M)
    const int wn   = wid >> 1;           // 0..3 (N)

    // ---- cooperative gmem -> smem (coalesced 16B, padded rows) ----
    {
        const uint4* a = (const uint4*)(g_a + (size_t)m0 * DD);
        const uint4* b = (const uint4*)(g_b + (size_t)n0 * DD);
        #pragma unroll
        for (int it = 0; it < 8; it++) {
            int c = tid + it * 256;          // 0..2047
            int r = c >> 4, q = c & 15;      // row, 8-half chunk
            *(uint4*)&Asm[r * S + q * 8] = a[c];
            *(uint4*)&Bsm[r * S + q * 8] = b[c];
        }
    }
    __syncthreads();

    float acc[4][4][4];
    #pragma unroll
    for (int i = 0; i < 4; i++)
        #pragma unroll
        for (int j = 0; j < 4; j++)
            #pragma unroll
            for (int x = 0; x < 4; x++) acc[i][j][x] = 0.0f;

    const uint32_t a_base = smem_u32(Asm);
    const uint32_t b_base = smem_u32(Bsm);
    const uint32_t aoff = ((uint32_t)((wm * 64 + (lane & 15)) * S + (lane >> 4) * 8)) * 2;
    const uint32_t boff = ((uint32_t)((wn * 32 + (lane & 15)) * S + (lane >> 4) * 8)) * 2;

    #pragma unroll
    for (int ks = 0; ks < 8; ks++) {
        const uint32_t kb = (uint32_t)(ks * 16) * 2;   // byte offset along K
        uint32_t af[4][4];
        #pragma unroll
        for (int mi = 0; mi < 4; mi++) {
            uint32_t addr = a_base + aoff + (uint32_t)(mi * 16 * S) * 2 + kb;
            asm volatile("ldmatrix.sync.aligned.m8n8.x4.shared.b16 {%0,%1,%2,%3}, [%4];"
                         : "=r"(af[mi][0]), "=r"(af[mi][1]), "=r"(af[mi][2]), "=r"(af[mi][3])
                         : "r"(addr));
        }
        uint32_t bf[2][4];
        #pragma unroll
        for (int np = 0; np < 2; np++) {
            uint32_t addr = b_base + boff + (uint32_t)(np * 16 * S) * 2 + kb;
            asm volatile("ldmatrix.sync.aligned.m8n8.x4.shared.b16 {%0,%1,%2,%3}, [%4];"
                         : "=r"(bf[np][0]), "=r"(bf[np][1]), "=r"(bf[np][2]), "=r"(bf[np][3])
                         : "r"(addr));
        }
        #pragma unroll
        for (int mi = 0; mi < 4; mi++) {
            #pragma unroll
            for (int ni = 0; ni < 4; ni++) {
                uint32_t b0 = bf[ni >> 1][ni & 1];
                uint32_t b1 = bf[ni >> 1][(ni & 1) + 2];
                asm volatile(
                    "mma.sync.aligned.m16n8k16.row.col.f32.f16.f16.f32 "
                    "{%0,%1,%2,%3}, {%4,%5,%6,%7}, {%8,%9}, {%0,%1,%2,%3};"
                    : "+f"(acc[mi][ni][0]), "+f"(acc[mi][ni][1]),
                      "+f"(acc[mi][ni][2]), "+f"(acc[mi][ni][3])
                    : "r"(af[mi][0]), "r"(af[mi][1]), "r"(af[mi][2]), "r"(af[mi][3]),
                      "r"(b0), "r"(b1));
            }
        }
    }

    // ---- epilogue: store dots col-major + fused per-row 32-col max ----
    const int g  = lane >> 2;
    const int tc = (lane & 3) * 2;
    const bool tail = (blockIdx.x == NTILES - 1);
    const int chunk = blockIdx.x * 4 + wn;

    #pragma unroll
    for (int mi = 0; mi < 4; mi++) {
        const int r1 = m0 + wm * 64 + mi * 16 + g;       // rows r1, r1+8
        float mx0 = -3.0e38f, mx1 = -3.0e38f;
        #pragma unroll
        for (int ni = 0; ni < 4; ni++) {
            const int col = n0 + wn * 32 + ni * 8 + tc;
            float v0 = acc[mi][ni][0], v1 = acc[mi][ni][1];
            float w0 = acc[mi][ni][2], w1 = acc[mi][ni][3];
            if (tail) {
                if (col     >= MREF) { v0 = -3.0e38f; w0 = -3.0e38f; }
                if (col + 1 >= MREF) { v1 = -3.0e38f; w1 = -3.0e38f; }
            }
            g_dotsT[(size_t) col      * NQ + r1    ] = v0;
            g_dotsT[(size_t)(col + 1) * NQ + r1    ] = v1;
            g_dotsT[(size_t) col      * NQ + r1 + 8] = w0;
            g_dotsT[(size_t)(col + 1) * NQ + r1 + 8] = w1;
            mx0 = fmaxf(mx0, fmaxf(v0, v1));
            mx1 = fmaxf(mx1, fmaxf(w0, w1));
        }
        mx0 = fmaxf(mx0, __shfl_xor_sync(0xffffffffu, mx0, 1));
        mx0 = fmaxf(mx0, __shfl_xor_sync(0xffffffffu, mx0, 2));
        mx1 = fmaxf(mx1, __shfl_xor_sync(0xffffffffu, mx1, 1));
        mx1 = fmaxf(mx1, __shfl_xor_sync(0xffffffffu, mx1, 2));
        if ((lane & 3) == 0) {
            g_gmax[(size_t)chunk * NQ + r1    ] = mx0;
            g_gmax[(size_t)chunk * NQ + r1 + 8] = mx1;
        }
    }
}

// ---------------- 3) block-parallel exact selection (1 block / query) ----------------
__global__ void __launch_bounds__(256, 4) phase2_select(const int* __restrict__ kptr,
                                                        float* __restrict__ out) {
    const int q = blockIdx.x;
    const int t = threadIdx.x;
    int kk = kptr[0] + 1;
    kk = kk < 1 ? 1 : (kk > 16 ? 16 : kk);

    __shared__ float smax[NCHUNK];           // working copy, extraction marks -inf
    __shared__ float cand[CANDMAX];
    __shared__ float rv[8];
    __shared__ int   ri[8];
    __shared__ int   n_cand;
    __shared__ float s_ext;

    for (int c = t; c < NCHUNK; c += 256) smax[c] = g_gmax[(size_t)c * NQ + q];
    if (t == 0) n_cand = 0;
    __syncthreads();

    // ---- kk rounds of block argmax extraction over chunk maxima -> lb ----
    for (int it = 0; it < kk; it++) {
        float bm = -3.4e38f; int bi = 0;
        for (int c = t; c < NCHUNK; c += 256) {
            float v = smax[c];
            if (v > bm) { bm = v; bi = c; }
        }
        #pragma unroll
        for (int o = 16; o > 0; o >>= 1) {
            float ov = __shfl_xor_sync(0xffffffffu, bm, o);
            int   oi = __shfl_xor_sync(0xffffffffu, bi, o);
            if (ov > bm) { bm = ov; bi = oi; }
        }
        if ((t & 31) == 0) { rv[t >> 5] = bm; ri[t >> 5] = bi; }
        __syncthreads();
        if (t == 0) {
            float m = rv[0]; int mi = ri[0];
            #pragma unroll
            for (int w = 1; w < 8; w++) if (rv[w] > m) { m = rv[w]; mi = ri[w]; }
            smax[mi] = -3.4e38f;
            s_ext = m;
        }
        __syncthreads();
    }
    const float lb = s_ext;                  // kk-th largest chunk max <= d_(kk)

    // ---- gather all dots >= lb from chunks whose (original) max >= lb ----
    for (int c = t; c < NCHUNK; c += 256) {
        float m = g_gmax[(size_t)c * NQ + q];
        if (m >= lb) {
            const float* base = g_dotsT + (size_t)c * CHUNK * NQ + q;
            #pragma unroll 4
            for (int j = 0; j < CHUNK; j++) {
                float v = base[(size_t)j * NQ];
                if (v >= lb) {
                    int p = atomicAdd(&n_cand, 1);
                    if (p < CANDMAX) cand[p] = v;
                }
            }
        }
    }
    __syncthreads();

    int nc = n_cand;
    if (nc > CANDMAX) {
        // ---- fallback (pathological ties): per-thread top-16 over full row ----
        float top[16];
        #pragma unroll
        for (int i = 0; i < 16; i++) top[i] = -3.4e38f;
        const float* row = g_dotsT + q;
        for (int m = t; m < MREF; m += 256) {
            float v = row[(size_t)m * NQ];
            if (v > top[15]) {
                top[15] = v;
                #pragma unroll
                for (int i = 15; i > 0; i--) {
                    if (top[i] > top[i - 1]) { float tv = top[i-1]; top[i-1] = top[i]; top[i] = tv; }
                }
            }
        }
        __syncthreads();
        #pragma unroll
        for (int i = 0; i < 16; i++) cand[t * 16 + i] = top[i];
        __syncthreads();
        nc = CANDMAX;
    }

    // ---- kk rounds of block argmax extraction over candidates -> exact kth ----
    for (int it = 0; it < kk; it++) {
        float bm = -3.4e38f; int bi = 0;
        for (int c = t; c < nc; c += 256) {
            float v = cand[c];
            if (v > bm) { bm = v; bi = c; }
        }
        #pragma unroll
        for (int o = 16; o > 0; o >>= 1) {
            float ov = __shfl_xor_sync(0xffffffffu, bm, o);
            int   oi = __shfl_xor_sync(0xffffffffu, bi, o);
            if (ov > bm) { bm = ov; bi = oi; }
        }
        if ((t & 31) == 0) { rv[t >> 5] = bm; ri[t >> 5] = bi; }
        __syncthreads();
        if (t == 0) {
            float m = rv[0]; int mi = ri[0];
            #pragma unroll
            for (int w = 1; w < 8; w++) if (rv[w] > m) { m = rv[w]; mi = ri[w]; }
            cand[mi] = -3.4e38f;
            s_ext = m;
        }
        __syncthreads();
    }

    if (t == 0) {
        float kth = s_ext;
        out[q] = sqrtf(fmaxf(2.0f - 2.0f * kth, 1e-12f));
    }
}

// ---------------- launch ----------------
extern "C" void kernel_launch(void* const* d_in, const int* in_sizes, int n_in,
                              void* d_out, int out_size) {
    const float* z    = (const float*)d_in[0];   // [2048,128]
    const float* ref  = (const float*)d_in[1];   // [50000,128]
    const int*   kptr = (const int*)d_in[2];     // scalar k
    float*       out  = (float*)d_out;           // [2048]

    const int smem_bytes = 2 * 128 * S * (int)sizeof(__half);   // 69632
    cudaFuncSetAttribute(knn_gemm, cudaFuncAttributeMaxDynamicSharedMemorySize, smem_bytes);

    normalize_rows<<<NQ,   128>>>(z,   NQ,   0);
    normalize_rows<<<MREF, 128>>>(ref, MREF, 1);

    dim3 grid(NTILES, 16);
    knn_gemm<<<grid, 256, smem_bytes>>>();

    phase2_select<<<NQ, 256>>>(kptr, out);
}

// round 7
// speedup vs baseline: 4.4996x; 1.7031x over previous
#include <cuda_runtime.h>
#include <cuda_fp16.h>
#include <stdint.h>
#include <math.h>

#define NQ     2048
#define MREF   50000
#define DD     128
#define NPAD   50048              // 391 * 128
#define NTILES 391
#define CHUNK  32
#define NCHUNK (NPAD / CHUNK)     // 1564
#define NCP    1568               // padded stride for g_gmaxT rows
#define S      136                // padded smem row stride in halfs (272 B)
#define CANDMAX 4096
#define CLISTMAX 256
#define EPS2   2.0e-3f            // 2x upper bound on |HMMA dot - recomputed dot|

// ---------------- static device scratch (allocation-free) ----------------
__device__ __align__(16) __half g_a[NQ * DD];             // normalized queries, fp16
__device__ __align__(16) __half g_b[NPAD * DD];           // normalized refs, zero-padded
__device__ float g_gmaxT[(size_t)NQ * NCP];               // per-query per-chunk max (12.8 MB)

__device__ __forceinline__ uint32_t smem_u32(const void* p) {
    uint32_t a;
    asm("{ .reg .u64 t; cvta.to.shared.u64 t, %1; cvt.u32.u64 %0, t; }" : "=r"(a) : "l"(p));
    return a;
}

// ---------------- 1) normalize rows -> fp16 (warp per row, float4) ----------------
__global__ void normalize_rows(const float* __restrict__ in, int rows, int which) {
    int row = blockIdx.x * 8 + (threadIdx.x >> 5);
    if (row >= rows) return;
    int lane = threadIdx.x & 31;
    float4 v = *(const float4*)&in[row * DD + lane * 4];
    float s = v.x * v.x + v.y * v.y + v.z * v.z + v.w * v.w;
    #pragma unroll
    for (int o = 16; o > 0; o >>= 1) s += __shfl_xor_sync(0xffffffffu, s, o);
    float inv = rsqrtf(s);
    __half2 h0 = __floats2half2_rn(v.x * inv, v.y * inv);
    __half2 h1 = __floats2half2_rn(v.z * inv, v.w * inv);
    __half2* dst = (__half2*)((which ? g_b : g_a) + row * DD + lane * 4);
    dst[0] = h0; dst[1] = h1;
}

// ---------------- 2) HMMA GEMM -> per-chunk max only ----------------
// grid (391, 16), 256 threads (8 warps, 2x4 warp grid), warp tile 64x32, K=128 resident
__global__ void __launch_bounds__(256, 2) knn_gemm() {
    extern __shared__ __align__(16) __half sm[];
    __half* Asm = sm;                    // [128][S]
    __half* Bsm = sm + 128 * S;          // [128][S]
    __shared__ float sgm[128][4];        // staged per-row chunk maxima

    const int tid  = threadIdx.x;
    const int wid  = tid >> 5, lane = tid & 31;
    const int n0   = blockIdx.x * 128, m0 = blockIdx.y * 128;
    const int wm   = wid & 1;            // 0..1 (M)
    const int wn   = wid >> 1;           // 0..3 (N)

    // ---- cooperative gmem -> smem (coalesced 16B, padded rows) ----
    {
        const uint4* a = (const uint4*)(g_a + (size_t)m0 * DD);
        const uint4* b = (const uint4*)(g_b + (size_t)n0 * DD);
        #pragma unroll
        for (int it = 0; it < 8; it++) {
            int c = tid + it * 256;          // 0..2047
            int r = c >> 4, q = c & 15;      // row, 8-half chunk
            *(uint4*)&Asm[r * S + q * 8] = a[c];
            *(uint4*)&Bsm[r * S + q * 8] = b[c];
        }
    }
    __syncthreads();

    float acc[4][4][4];
    #pragma unroll
    for (int i = 0; i < 4; i++)
        #pragma unroll
        for (int j = 0; j < 4; j++)
            #pragma unroll
            for (int x = 0; x < 4; x++) acc[i][j][x] = 0.0f;

    const uint32_t a_base = smem_u32(Asm);
    const uint32_t b_base = smem_u32(Bsm);
    const uint32_t aoff = ((uint32_t)((wm * 64 + (lane & 15)) * S + (lane >> 4) * 8)) * 2;
    const uint32_t boff = ((uint32_t)((wn * 32 + (lane & 15)) * S + (lane >> 4) * 8)) * 2;

    #pragma unroll
    for (int ks = 0; ks < 8; ks++) {
        const uint32_t kb = (uint32_t)(ks * 16) * 2;   // byte offset along K
        uint32_t af[4][4];
        #pragma unroll
        for (int mi = 0; mi < 4; mi++) {
            uint32_t addr = a_base + aoff + (uint32_t)(mi * 16 * S) * 2 + kb;
            asm volatile("ldmatrix.sync.aligned.m8n8.x4.shared.b16 {%0,%1,%2,%3}, [%4];"
                         : "=r"(af[mi][0]), "=r"(af[mi][1]), "=r"(af[mi][2]), "=r"(af[mi][3])
                         : "r"(addr));
        }
        uint32_t bf[2][4];
        #pragma unroll
        for (int np = 0; np < 2; np++) {
            uint32_t addr = b_base + boff + (uint32_t)(np * 16 * S) * 2 + kb;
            asm volatile("ldmatrix.sync.aligned.m8n8.x4.shared.b16 {%0,%1,%2,%3}, [%4];"
                         : "=r"(bf[np][0]), "=r"(bf[np][1]), "=r"(bf[np][2]), "=r"(bf[np][3])
                         : "r"(addr));
        }
        #pragma unroll
        for (int mi = 0; mi < 4; mi++) {
            #pragma unroll
            for (int ni = 0; ni < 4; ni++) {
                uint32_t b0 = bf[ni >> 1][ni & 1];
                uint32_t b1 = bf[ni >> 1][(ni & 1) + 2];
                asm volatile(
                    "mma.sync.aligned.m16n8k16.row.col.f32.f16.f16.f32 "
                    "{%0,%1,%2,%3}, {%4,%5,%6,%7}, {%8,%9}, {%0,%1,%2,%3};"
                    : "+f"(acc[mi][ni][0]), "+f"(acc[mi][ni][1]),
                      "+f"(acc[mi][ni][2]), "+f"(acc[mi][ni][3])
                    : "r"(af[mi][0]), "r"(af[mi][1]), "r"(af[mi][2]), "r"(af[mi][3]),
                      "r"(b0), "r"(b1));
            }
        }
    }

    // ---- epilogue: per-row max over this warp's 32 cols -> sgm -> coalesced store ----
    const int g  = lane >> 2;
    const int tc = (lane & 3) * 2;
    const bool tail = (blockIdx.x == NTILES - 1);

    #pragma unroll
    for (int mi = 0; mi < 4; mi++) {
        const int lr = wm * 64 + mi * 16 + g;            // local rows lr, lr+8
        float mx0 = -3.0e38f, mx1 = -3.0e38f;
        #pragma unroll
        for (int ni = 0; ni < 4; ni++) {
            const int col = n0 + wn * 32 + ni * 8 + tc;
            float v0 = acc[mi][ni][0], v1 = acc[mi][ni][1];
            float w0 = acc[mi][ni][2], w1 = acc[mi][ni][3];
            if (tail) {
                if (col     >= MREF) { v0 = -3.0e38f; w0 = -3.0e38f; }
                if (col + 1 >= MREF) { v1 = -3.0e38f; w1 = -3.0e38f; }
            }
            mx0 = fmaxf(mx0, fmaxf(v0, v1));
            mx1 = fmaxf(mx1, fmaxf(w0, w1));
        }
        mx0 = fmaxf(mx0, __shfl_xor_sync(0xffffffffu, mx0, 1));
        mx0 = fmaxf(mx0, __shfl_xor_sync(0xffffffffu, mx0, 2));
        mx1 = fmaxf(mx1, __shfl_xor_sync(0xffffffffu, mx1, 1));
        mx1 = fmaxf(mx1, __shfl_xor_sync(0xffffffffu, mx1, 2));
        if ((lane & 3) == 0) {
            sgm[lr][wn]     = mx0;
            sgm[lr + 8][wn] = mx1;
        }
    }
    __syncthreads();
    if (tid < 128) {
        float4 v = *(float4*)sgm[tid];
        *(float4*)&g_gmaxT[(size_t)(m0 + tid) * NCP + blockIdx.x * 4] = v;
    }
}

// ---------------- 3) block-parallel exact selection with dot recompute ----------------
__global__ void __launch_bounds__(256, 4) phase2_select(const int* __restrict__ kptr,
                                                        float* __restrict__ out) {
    const int q = blockIdx.x;
    const int t = threadIdx.x;
    int kk = kptr[0] + 1;
    kk = kk < 1 ? 1 : (kk > 16 ? 16 : kk);

    __shared__ float smax[NCHUNK];
    __shared__ float aq[DD];
    __shared__ float cand[CANDMAX];
    __shared__ int   clist[CLISTMAX];
    __shared__ float rv[8];
    __shared__ int   ri[8];
    __shared__ int   ncc, n_cand;
    __shared__ float s_ext;
    __shared__ float sav_v[16];
    __shared__ int   sav_i[16];

    for (int c = t; c < NCHUNK; c += 256) smax[c] = g_gmaxT[(size_t)q * NCP + c];
    if (t < DD) aq[t] = __half2float(g_a[q * DD + t]);
    if (t == 0) { ncc = 0; n_cand = 0; }
    __syncthreads();

    // ---- kk extraction rounds over chunk maxima -> lb (saving extracted for restore) ----
    for (int it = 0; it < kk; it++) {
        float bm = -3.4e38f; int bi = 0;
        for (int c = t; c < NCHUNK; c += 256) {
            float v = smax[c];
            if (v > bm) { bm = v; bi = c; }
        }
        #pragma unroll
        for (int o = 16; o > 0; o >>= 1) {
            float ov = __shfl_xor_sync(0xffffffffu, bm, o);
            int   oi = __shfl_xor_sync(0xffffffffu, bi, o);
            if (ov > bm) { bm = ov; bi = oi; }
        }
        if ((t & 31) == 0) { rv[t >> 5] = bm; ri[t >> 5] = bi; }
        __syncthreads();
        if (t == 0) {
            float m = rv[0]; int mi = ri[0];
            #pragma unroll
            for (int w = 1; w < 8; w++) if (rv[w] > m) { m = rv[w]; mi = ri[w]; }
            smax[mi] = -3.4e38f;
            sav_i[it] = mi; sav_v[it] = m;
            s_ext = m;
        }
        __syncthreads();
    }
    const float thr = s_ext - EPS2;
    if (t < kk) smax[sav_i[t]] = sav_v[t];          // restore extracted maxima
    __syncthreads();

    // ---- candidate chunk list ----
    for (int c = t; c < NCHUNK; c += 256) {
        if (smax[c] >= thr) {
            int p = atomicAdd(&ncc, 1);
            if (p < CLISTMAX) clist[p] = c;
        }
    }
    __syncthreads();

    const int nchunks = ncc < CLISTMAX ? ncc : CLISTMAX;
    bool overflow = (ncc > CLISTMAX);

    // ---- recompute candidate dots, gather those >= thr ----
    if (!overflow) {
        for (int idx = t; idx < nchunks * CHUNK; idx += 256) {
            int c   = clist[idx >> 5];
            int ref = c * CHUNK + (idx & 31);
            if (ref < MREF) {
                const __half2* b = (const __half2*)(g_b + (size_t)ref * DD);
                float dot = 0.0f;
                #pragma unroll
                for (int d = 0; d < 64; d++) {
                    float2 bb = __half22float2(b[d]);
                    dot += aq[2 * d] * bb.x + aq[2 * d + 1] * bb.y;
                }
                if (dot >= thr) {
                    int p = atomicAdd(&n_cand, 1);
                    if (p < CANDMAX) cand[p] = dot;
                }
            }
        }
        __syncthreads();
    }

    int nc = n_cand;
    if (overflow || nc > CANDMAX) {
        // ---- fallback (pathological ties): exhaustive recompute, per-thread top-16 ----
        __syncthreads();
        float top[16];
        #pragma unroll
        for (int i = 0; i < 16; i++) top[i] = -3.4e38f;
        for (int ref = t; ref < MREF; ref += 256) {
            const __half2* b = (const __half2*)(g_b + (size_t)ref * DD);
            float dot = 0.0f;
            #pragma unroll
            for (int d = 0; d < 64; d++) {
                float2 bb = __half22float2(b[d]);
                dot += aq[2 * d] * bb.x + aq[2 * d + 1] * bb.y;
            }
            if (dot > top[15]) {
                top[15] = dot;
                #pragma unroll
                for (int i = 15; i > 0; i--) {
                    if (top[i] > top[i - 1]) { float tv = top[i-1]; top[i-1] = top[i]; top[i] = tv; }
                }
            }
        }
        __syncthreads();
        #pragma unroll
        for (int i = 0; i < 16; i++) cand[t * 16 + i] = top[i];
        __syncthreads();
        nc = CANDMAX;
    }

    // ---- kk extraction rounds over candidates -> exact kth ----
    for (int it = 0; it < kk; it++) {
        float bm = -3.4e38f; int bi = 0;
        for (int c = t; c < nc; c += 256) {
            float v = cand[c];
            if (v > bm) { bm = v; bi = c; }
        }
        #pragma unroll
        for (int o = 16; o > 0; o >>= 1) {
            float ov = __shfl_xor_sync(0xffffffffu, bm, o);
            int   oi = __shfl_xor_sync(0xffffffffu, bi, o);
            if (ov > bm) { bm = ov; bi = oi; }
        }
        if ((t & 31) == 0) { rv[t >> 5] = bm; ri[t >> 5] = bi; }
        __syncthreads();
        if (t == 0) {
            float m = rv[0]; int mi = ri[0];
            #pragma unroll
            for (int w = 1; w < 8; w++) if (rv[w] > m) { m = rv[w]; mi = ri[w]; }
            cand[mi] = -3.4e38f;
            s_ext = m;
        }
        __syncthreads();
    }

    if (t == 0) {
        float kth = s_ext;
        out[q] = sqrtf(fmaxf(2.0f - 2.0f * kth, 1e-12f));
    }
}

// ---------------- launch ----------------
extern "C" void kernel_launch(void* const* d_in, const int* in_sizes, int n_in,
                              void* d_out, int out_size) {
    const float* z    = (const float*)d_in[0];   // [2048,128]
    const float* ref  = (const float*)d_in[1];   // [50000,128]
    const int*   kptr = (const int*)d_in[2];     // scalar k
    float*       out  = (float*)d_out;           // [2048]

    const int smem_bytes = 2 * 128 * S * (int)sizeof(__half);   // 69632
    cudaFuncSetAttribute(knn_gemm, cudaFuncAttributeMaxDynamicSharedMemorySize, smem_bytes);

    normalize_rows<<<NQ / 8, 256>>>(z, NQ, 0);
    normalize_rows<<<(MREF + 7) / 8, 256>>>(ref, MREF, 1);

    dim3 grid(NTILES, 16);
    knn_gemm<<<grid, 256, smem_bytes>>>();

    phase2_select<<<NQ, 256>>>(kptr, out);
}

// round 8
// speedup vs baseline: 5.0473x; 1.1217x over previous
#include <cuda_runtime.h>
#include <cuda_fp16.h>
#include <stdint.h>
#include <math.h>

#define NQ     2048
#define MREF   50000
#define DD     128
#define NPAD   50048              // 391 * 128
#define NTILES 391
#define CHUNK  32
#define NCHUNK (NPAD / CHUNK)     // 1564
#define NCP    1568               // padded stride for g_gmaxT rows
#define S      136                // padded smem row stride in halfs (272 B)
#define CANDMAX 4096
#define CLISTMAX 256
#define EPS2   2.0e-3f            // margin: |HMMA dot - recomputed dot| bound (generous)
#define HBINS  256
#define HRANGE 0.5f
#define HW     (HRANGE / HBINS)   // bin width ~1.95e-3

// ---------------- static device scratch (allocation-free) ----------------
__device__ __align__(16) __half g_a[NQ * DD];             // normalized queries, fp16
__device__ __align__(16) __half g_b[NPAD * DD];           // normalized refs, zero-padded
__device__ float g_gmaxT[(size_t)NQ * NCP];               // per-query per-chunk max (12.8 MB)

__device__ __forceinline__ uint32_t smem_u32(const void* p) {
    uint32_t a;
    asm("{ .reg .u64 t; cvta.to.shared.u64 t, %1; cvt.u32.u64 %0, t; }" : "=r"(a) : "l"(p));
    return a;
}

// ---------------- 1) normalize rows -> fp16 (warp per row, float4) ----------------
__global__ void normalize_rows(const float* __restrict__ in, int rows, int which) {
    int row = blockIdx.x * 8 + (threadIdx.x >> 5);
    if (row >= rows) return;
    int lane = threadIdx.x & 31;
    float4 v = *(const float4*)&in[row * DD + lane * 4];
    float s = v.x * v.x + v.y * v.y + v.z * v.z + v.w * v.w;
    #pragma unroll
    for (int o = 16; o > 0; o >>= 1) s += __shfl_xor_sync(0xffffffffu, s, o);
    float inv = rsqrtf(s);
    __half2 h0 = __floats2half2_rn(v.x * inv, v.y * inv);
    __half2 h1 = __floats2half2_rn(v.z * inv, v.w * inv);
    __half2* dst = (__half2*)((which ? g_b : g_a) + row * DD + lane * 4);
    dst[0] = h0; dst[1] = h1;
}

// ---------------- 2) HMMA GEMM -> per-chunk max only ----------------
// grid (391, 16), 256 threads (8 warps, 2x4 warp grid), warp tile 64x32, K=128 resident
__global__ void __launch_bounds__(256, 2) knn_gemm() {
    extern __shared__ __align__(16) __half sm[];
    __half* Asm = sm;                    // [128][S]
    __half* Bsm = sm + 128 * S;          // [128][S]
    __shared__ float sgm[128][4];        // staged per-row chunk maxima

    const int tid  = threadIdx.x;
    const int wid  = tid >> 5, lane = tid & 31;
    const int n0   = blockIdx.x * 128, m0 = blockIdx.y * 128;
    const int wm   = wid & 1;            // 0..1 (M)
    const int wn   = wid >> 1;           // 0..3 (N)

    {
        const uint4* a = (const uint4*)(g_a + (size_t)m0 * DD);
        const uint4* b = (const uint4*)(g_b + (size_t)n0 * DD);
        #pragma unroll
        for (int it = 0; it < 8; it++) {
            int c = tid + it * 256;
            int r = c >> 4, q = c & 15;
            *(uint4*)&Asm[r * S + q * 8] = a[c];
            *(uint4*)&Bsm[r * S + q * 8] = b[c];
        }
    }
    __syncthreads();

    float acc[4][4][4];
    #pragma unroll
    for (int i = 0; i < 4; i++)
        #pragma unroll
        for (int j = 0; j < 4; j++)
            #pragma unroll
            for (int x = 0; x < 4; x++) acc[i][j][x] = 0.0f;

    const uint32_t a_base = smem_u32(Asm);
    const uint32_t b_base = smem_u32(Bsm);
    const uint32_t aoff = ((uint32_t)((wm * 64 + (lane & 15)) * S + (lane >> 4) * 8)) * 2;
    const uint32_t boff = ((uint32_t)((wn * 32 + (lane & 15)) * S + (lane >> 4) * 8)) * 2;

    #pragma unroll
    for (int ks = 0; ks < 8; ks++) {
        const uint32_t kb = (uint32_t)(ks * 16) * 2;
        uint32_t af[4][4];
        #pragma unroll
        for (int mi = 0; mi < 4; mi++) {
            uint32_t addr = a_base + aoff + (uint32_t)(mi * 16 * S) * 2 + kb;
            asm volatile("ldmatrix.sync.aligned.m8n8.x4.shared.b16 {%0,%1,%2,%3}, [%4];"
                         : "=r"(af[mi][0]), "=r"(af[mi][1]), "=r"(af[mi][2]), "=r"(af[mi][3])
                         : "r"(addr));
        }
        uint32_t bf[2][4];
        #pragma unroll
        for (int np = 0; np < 2; np++) {
            uint32_t addr = b_base + boff + (uint32_t)(np * 16 * S) * 2 + kb;
            asm volatile("ldmatrix.sync.aligned.m8n8.x4.shared.b16 {%0,%1,%2,%3}, [%4];"
                         : "=r"(bf[np][0]), "=r"(bf[np][1]), "=r"(bf[np][2]), "=r"(bf[np][3])
                         : "r"(addr));
        }
        #pragma unroll
        for (int mi = 0; mi < 4; mi++) {
            #pragma unroll
            for (int ni = 0; ni < 4; ni++) {
                uint32_t b0 = bf[ni >> 1][ni & 1];
                uint32_t b1 = bf[ni >> 1][(ni & 1) + 2];
                asm volatile(
                    "mma.sync.aligned.m16n8k16.row.col.f32.f16.f16.f32 "
                    "{%0,%1,%2,%3}, {%4,%5,%6,%7}, {%8,%9}, {%0,%1,%2,%3};"
                    : "+f"(acc[mi][ni][0]), "+f"(acc[mi][ni][1]),
                      "+f"(acc[mi][ni][2]), "+f"(acc[mi][ni][3])
                    : "r"(af[mi][0]), "r"(af[mi][1]), "r"(af[mi][2]), "r"(af[mi][3]),
                      "r"(b0), "r"(b1));
            }
        }
    }

    const int g  = lane >> 2;
    const int tc = (lane & 3) * 2;
    const bool tail = (blockIdx.x == NTILES - 1);

    #pragma unroll
    for (int mi = 0; mi < 4; mi++) {
        const int lr = wm * 64 + mi * 16 + g;
        float mx0 = -3.0e38f, mx1 = -3.0e38f;
        #pragma unroll
        for (int ni = 0; ni < 4; ni++) {
            const int col = n0 + wn * 32 + ni * 8 + tc;
            float v0 = acc[mi][ni][0], v1 = acc[mi][ni][1];
            float w0 = acc[mi][ni][2], w1 = acc[mi][ni][3];
            if (tail) {
                if (col     >= MREF) { v0 = -3.0e38f; w0 = -3.0e38f; }
                if (col + 1 >= MREF) { v1 = -3.0e38f; w1 = -3.0e38f; }
            }
            mx0 = fmaxf(mx0, fmaxf(v0, v1));
            mx1 = fmaxf(mx1, fmaxf(w0, w1));
        }
        mx0 = fmaxf(mx0, __shfl_xor_sync(0xffffffffu, mx0, 1));
        mx0 = fmaxf(mx0, __shfl_xor_sync(0xffffffffu, mx0, 2));
        mx1 = fmaxf(mx1, __shfl_xor_sync(0xffffffffu, mx1, 1));
        mx1 = fmaxf(mx1, __shfl_xor_sync(0xffffffffu, mx1, 2));
        if ((lane & 3) == 0) {
            sgm[lr][wn]     = mx0;
            sgm[lr + 8][wn] = mx1;
        }
    }
    __syncthreads();
    if (tid < 128) {
        float4 v = *(float4*)sgm[tid];
        *(float4*)&g_gmaxT[(size_t)(m0 + tid) * NCP + blockIdx.x * 4] = v;
    }
}

// ---------------- 3) histogram-threshold exact selection (1 block / query) ----------------
__global__ void __launch_bounds__(256, 4) phase2_select(const int* __restrict__ kptr,
                                                        float* __restrict__ out) {
    const int q = blockIdx.x;
    const int t = threadIdx.x;
    const int lane = t & 31;
    int kk = kptr[0] + 1;
    kk = kk < 1 ? 1 : (kk > 16 ? 16 : kk);

    __shared__ float smax[NCHUNK];
    __shared__ float aq[DD];
    __shared__ int   hist[HBINS];
    __shared__ float cand[CANDMAX];
    __shared__ int   clist[CLISTMAX];
    __shared__ float red[8];
    __shared__ int   ncc, n_cand, s_fb;
    __shared__ float s_thr, s_res;

    for (int c = t; c < NCHUNK; c += 256) smax[c] = g_gmaxT[(size_t)q * NCP + c];
    if (t < DD) aq[t] = __half2float(g_a[q * DD + t]);
    hist[t] = 0;
    if (t == 0) { ncc = 0; n_cand = 0; s_fb = 0; }
    __syncthreads();

    // ---- block max of chunk maxima ----
    float bm = -3.4e38f;
    for (int c = t; c < NCHUNK; c += 256) bm = fmaxf(bm, smax[c]);
    #pragma unroll
    for (int o = 16; o > 0; o >>= 1) bm = fmaxf(bm, __shfl_xor_sync(0xffffffffu, bm, o));
    if (lane == 0) red[t >> 5] = bm;
    __syncthreads();
    float M = red[0];
    #pragma unroll
    for (int w = 1; w < 8; w++) M = fmaxf(M, red[w]);

    // ---- histogram of (M - v) over [0, HRANGE) ----
    const float invW = 1.0f / HW;
    for (int c = t; c < NCHUNK; c += 256) {
        float d = M - smax[c];
        int b = (int)(d * invW);
        if (b < 0) b = 0;
        if (b < HBINS) atomicAdd(&hist[b], 1);
    }
    __syncthreads();

    // ---- warp0: suffix scan (from bin 0 = highest value) -> first bin with cum >= kk ----
    if (t < 32) {
        int cnt[8], seg = 0;
        #pragma unroll
        for (int i = 0; i < 8; i++) { cnt[i] = hist[t * 8 + i]; seg += cnt[i]; }
        int inc = seg;
        #pragma unroll
        for (int o = 1; o < 32; o <<= 1) {
            int x = __shfl_up_sync(0xffffffffu, inc, o);
            if (lane >= o) inc += x;
        }
        int run = inc - seg;                 // exclusive prefix (bins above this segment)
        int bstar = 1 << 30;
        #pragma unroll
        for (int i = 0; i < 8; i++) {
            run += cnt[i];
            if (run >= kk && bstar == (1 << 30)) bstar = t * 8 + i;
        }
        #pragma unroll
        for (int o = 16; o > 0; o >>= 1) {
            int ob = __shfl_xor_sync(0xffffffffu, bstar, o);
            bstar = ob < bstar ? ob : bstar;
        }
        if (t == 0) {
            if (bstar >= HBINS) s_fb = 1;                       // kk-th below M-HRANGE: rare
            else s_thr = M - (float)(bstar + 1) * HW - EPS2;    // <= kk-th chunk max - EPS2
        }
    }
    __syncthreads();

    bool fallback = (s_fb != 0);
    const float thr = s_thr;

    // ---- candidate chunk list ----
    if (!fallback) {
        for (int c = t; c < NCHUNK; c += 256) {
            if (smax[c] >= thr) {
                int p = atomicAdd(&ncc, 1);
                if (p < CLISTMAX) clist[p] = c;
            }
        }
        __syncthreads();
        if (ncc > CLISTMAX) fallback = true;
    }

    // ---- recompute candidate dots, gather those >= thr ----
    if (!fallback) {
        const int nchunks = ncc;
        for (int idx = t; idx < nchunks * CHUNK; idx += 256) {
            int c   = clist[idx >> 5];
            int ref = c * CHUNK + (idx & 31);
            if (ref < MREF) {
                const __half2* b = (const __half2*)(g_b + (size_t)ref * DD);
                float dot = 0.0f;
                #pragma unroll
                for (int d = 0; d < 64; d++) {
                    float2 bb = __half22float2(b[d]);
                    dot += aq[2 * d] * bb.x + aq[2 * d + 1] * bb.y;
                }
                if (dot >= thr) {
                    int p = atomicAdd(&n_cand, 1);
                    if (p < CANDMAX) cand[p] = dot;
                }
            }
        }
        __syncthreads();
        if (n_cand > CANDMAX || n_cand < kk) fallback = true;
    }

    int nc = n_cand;
    if (fallback) {
        // ---- exhaustive recompute, per-thread top-16 (always correct) ----
        __syncthreads();
        float top[16];
        #pragma unroll
        for (int i = 0; i < 16; i++) top[i] = -3.4e38f;
        for (int ref = t; ref < MREF; ref += 256) {
            const __half2* b = (const __half2*)(g_b + (size_t)ref * DD);
            float dot = 0.0f;
            #pragma unroll
            for (int d = 0; d < 64; d++) {
                float2 bb = __half22float2(b[d]);
                dot += aq[2 * d] * bb.x + aq[2 * d + 1] * bb.y;
            }
            if (dot > top[15]) {
                top[15] = dot;
                #pragma unroll
                for (int i = 15; i > 0; i--) {
                    if (top[i] > top[i - 1]) { float tv = top[i-1]; top[i-1] = top[i]; top[i] = tv; }
                }
            }
        }
        __syncthreads();
        #pragma unroll
        for (int i = 0; i < 16; i++) cand[t * 16 + i] = top[i];
        __syncthreads();
        nc = CANDMAX;
    }

    // ---- warp0: exact kk-th largest via per-lane sorted lists + k-way shuffle merge ----
    if (t < 32) {
        float top[16];
        #pragma unroll
        for (int i = 0; i < 16; i++) top[i] = -3.4e38f;
        for (int c = t; c < nc; c += 32) {
            float v = cand[c];
            if (v > top[15]) {
                top[15] = v;
                #pragma unroll
                for (int i = 15; i > 0; i--) {
                    if (top[i] > top[i - 1]) { float tv = top[i-1]; top[i-1] = top[i]; top[i] = tv; }
                }
            }
        }
        float kth = -3.4e38f;
        for (int it = 0; it < kk; it++) {
            float v = top[0]; int bl = t;
            #pragma unroll
            for (int o = 16; o > 0; o >>= 1) {
                float ov = __shfl_xor_sync(0xffffffffu, v, o);
                int   ol = __shfl_xor_sync(0xffffffffu, bl, o);
                if (ov > v || (ov == v && ol < bl)) { v = ov; bl = ol; }
            }
            if (t == bl) {                      // winner pops its head (static shift)
                #pragma unroll
                for (int i = 0; i < 15; i++) top[i] = top[i + 1];
                top[15] = -3.4e38f;
            }
            kth = v;
        }
        if (t == 0) s_res = kth;
    }
    __syncthreads();

    if (t == 0) out[q] = sqrtf(fmaxf(2.0f - 2.0f * s_res, 1e-12f));
}

// ---------------- launch ----------------
extern "C" void kernel_launch(void* const* d_in, const int* in_sizes, int n_in,
                              void* d_out, int out_size) {
    const float* z    = (const float*)d_in[0];   // [2048,128]
    const float* ref  = (const float*)d_in[1];   // [50000,128]
    const int*   kptr = (const int*)d_in[2];     // scalar k
    float*       out  = (float*)d_out;           // [2048]

    const int smem_bytes = 2 * 128 * S * (int)sizeof(__half);   // 69632
    cudaFuncSetAttribute(knn_gemm, cudaFuncAttributeMaxDynamicSharedMemorySize, smem_bytes);

    normalize_rows<<<NQ / 8, 256>>>(z, NQ, 0);
    normalize_rows<<<(MREF + 7) / 8, 256>>>(ref, MREF, 1);

    dim3 grid(NTILES, 16);
    knn_gemm<<<grid, 256, smem_bytes>>>();

    phase2_select<<<NQ, 256>>>(kptr, out);
}

// round 9
// speedup vs baseline: 6.8095x; 1.3491x over previous
#include <cuda_runtime.h>
#include <cuda_fp16.h>
#include <stdint.h>
#include <math.h>

#define NQ     2048
#define MREF   50000
#define DD     128
#define NPAD   50048              // 391 * 128
#define NTILES 391
#define CHUNK  32
#define NCHUNK (NPAD / CHUNK)     // 1564
#define NCP    1568               // padded stride for g_gmaxT rows
#define S      136                // padded smem row stride in halfs (272 B)
#define CANDMAX 4096
#define CLISTMAX 256
#define EPS2   2.0e-3f            // margin: |HMMA dot - recomputed dot| bound (generous)
#define HBINS  256
#define HRANGE 0.5f
#define HW     (HRANGE / HBINS)   // bin width ~1.95e-3

// ---------------- static device scratch (allocation-free) ----------------
__device__ __align__(16) __half g_a[NQ * DD];             // normalized queries, fp16
__device__ __align__(16) __half g_b[NPAD * DD];           // normalized refs, zero-padded
__device__ float g_gmaxT[(size_t)NQ * NCP];               // per-query per-chunk max (12.8 MB)

__device__ __forceinline__ uint32_t smem_u32(const void* p) {
    uint32_t a;
    asm("{ .reg .u64 t; cvta.to.shared.u64 t, %1; cvt.u32.u64 %0, t; }" : "=r"(a) : "l"(p));
    return a;
}

// ---------------- 1) normalize rows -> fp16 (warp per row, float4) ----------------
__global__ void normalize_rows(const float* __restrict__ in, int rows, int which) {
    int row = blockIdx.x * 8 + (threadIdx.x >> 5);
    if (row >= rows) return;
    int lane = threadIdx.x & 31;
    float4 v = *(const float4*)&in[row * DD + lane * 4];
    float s = v.x * v.x + v.y * v.y + v.z * v.z + v.w * v.w;
    #pragma unroll
    for (int o = 16; o > 0; o >>= 1) s += __shfl_xor_sync(0xffffffffu, s, o);
    float inv = rsqrtf(s);
    __half2 h0 = __floats2half2_rn(v.x * inv, v.y * inv);
    __half2 h1 = __floats2half2_rn(v.z * inv, v.w * inv);
    __half2* dst = (__half2*)((which ? g_b : g_a) + row * DD + lane * 4);
    dst[0] = h0; dst[1] = h1;
}

// ---------------- 2) HMMA GEMM -> per-chunk max only ----------------
// grid (391, 16), 256 threads (8 warps, 2x4 warp grid), warp tile 64x32, K=128 resident
__global__ void __launch_bounds__(256, 2) knn_gemm() {
    extern __shared__ __align__(16) __half sm[];
    __half* Asm = sm;                    // [128][S]
    __half* Bsm = sm + 128 * S;          // [128][S]
    __shared__ float sgm[128][4];        // staged per-row chunk maxima

    const int tid  = threadIdx.x;
    const int wid  = tid >> 5, lane = tid & 31;
    const int n0   = blockIdx.x * 128, m0 = blockIdx.y * 128;
    const int wm   = wid & 1;            // 0..1 (M)
    const int wn   = wid >> 1;           // 0..3 (N)

    {
        const uint4* a = (const uint4*)(g_a + (size_t)m0 * DD);
        const uint4* b = (const uint4*)(g_b + (size_t)n0 * DD);
        #pragma unroll
        for (int it = 0; it < 8; it++) {
            int c = tid + it * 256;
            int r = c >> 4, q = c & 15;
            *(uint4*)&Asm[r * S + q * 8] = a[c];
            *(uint4*)&Bsm[r * S + q * 8] = b[c];
        }
    }
    __syncthreads();

    float acc[4][4][4];
    #pragma unroll
    for (int i = 0; i < 4; i++)
        #pragma unroll
        for (int j = 0; j < 4; j++)
            #pragma unroll
            for (int x = 0; x < 4; x++) acc[i][j][x] = 0.0f;

    const uint32_t a_base = smem_u32(Asm);
    const uint32_t b_base = smem_u32(Bsm);
    const uint32_t aoff = ((uint32_t)((wm * 64 + (lane & 15)) * S + (lane >> 4) * 8)) * 2;
    const uint32_t boff = ((uint32_t)((wn * 32 + (lane & 15)) * S + (lane >> 4) * 8)) * 2;

    #pragma unroll
    for (int ks = 0; ks < 8; ks++) {
        const uint32_t kb = (uint32_t)(ks * 16) * 2;
        uint32_t af[4][4];
        #pragma unroll
        for (int mi = 0; mi < 4; mi++) {
            uint32_t addr = a_base + aoff + (uint32_t)(mi * 16 * S) * 2 + kb;
            asm volatile("ldmatrix.sync.aligned.m8n8.x4.shared.b16 {%0,%1,%2,%3}, [%4];"
                         : "=r"(af[mi][0]), "=r"(af[mi][1]), "=r"(af[mi][2]), "=r"(af[mi][3])
                         : "r"(addr));
        }
        uint32_t bf[2][4];
        #pragma unroll
        for (int np = 0; np < 2; np++) {
            uint32_t addr = b_base + boff + (uint32_t)(np * 16 * S) * 2 + kb;
            asm volatile("ldmatrix.sync.aligned.m8n8.x4.shared.b16 {%0,%1,%2,%3}, [%4];"
                         : "=r"(bf[np][0]), "=r"(bf[np][1]), "=r"(bf[np][2]), "=r"(bf[np][3])
                         : "r"(addr));
        }
        #pragma unroll
        for (int mi = 0; mi < 4; mi++) {
            #pragma unroll
            for (int ni = 0; ni < 4; ni++) {
                uint32_t b0 = bf[ni >> 1][ni & 1];
                uint32_t b1 = bf[ni >> 1][(ni & 1) + 2];
                asm volatile(
                    "mma.sync.aligned.m16n8k16.row.col.f32.f16.f16.f32 "
                    "{%0,%1,%2,%3}, {%4,%5,%6,%7}, {%8,%9}, {%0,%1,%2,%3};"
                    : "+f"(acc[mi][ni][0]), "+f"(acc[mi][ni][1]),
                      "+f"(acc[mi][ni][2]), "+f"(acc[mi][ni][3])
                    : "r"(af[mi][0]), "r"(af[mi][1]), "r"(af[mi][2]), "r"(af[mi][3]),
                      "r"(b0), "r"(b1));
            }
        }
    }

    const int g  = lane >> 2;
    const int tc = (lane & 3) * 2;
    const bool tail = (blockIdx.x == NTILES - 1);

    #pragma unroll
    for (int mi = 0; mi < 4; mi++) {
        const int lr = wm * 64 + mi * 16 + g;
        float mx0 = -3.0e38f, mx1 = -3.0e38f;
        #pragma unroll
        for (int ni = 0; ni < 4; ni++) {
            const int col = n0 + wn * 32 + ni * 8 + tc;
            float v0 = acc[mi][ni][0], v1 = acc[mi][ni][1];
            float w0 = acc[mi][ni][2], w1 = acc[mi][ni][3];
            if (tail) {
                if (col     >= MREF) { v0 = -3.0e38f; w0 = -3.0e38f; }
                if (col + 1 >= MREF) { v1 = -3.0e38f; w1 = -3.0e38f; }
            }
            mx0 = fmaxf(mx0, fmaxf(v0, v1));
            mx1 = fmaxf(mx1, fmaxf(w0, w1));
        }
        mx0 = fmaxf(mx0, __shfl_xor_sync(0xffffffffu, mx0, 1));
        mx0 = fmaxf(mx0, __shfl_xor_sync(0xffffffffu, mx0, 2));
        mx1 = fmaxf(mx1, __shfl_xor_sync(0xffffffffu, mx1, 1));
        mx1 = fmaxf(mx1, __shfl_xor_sync(0xffffffffu, mx1, 2));
        if ((lane & 3) == 0) {
            sgm[lr][wn]     = mx0;
            sgm[lr + 8][wn] = mx1;
        }
    }
    __syncthreads();
    if (tid < 128) {
        float4 v = *(float4*)sgm[tid];
        *(float4*)&g_gmaxT[(size_t)(m0 + tid) * NCP + blockIdx.x * 4] = v;
    }
}

// ---------------- 3) histogram-threshold exact selection (1 block / query) ----------------
__global__ void __launch_bounds__(256, 6) phase2_select(const int* __restrict__ kptr,
                                                        float* __restrict__ out) {
    const int q = blockIdx.x;
    const int t = threadIdx.x;
    const int lane = t & 31;
    const int wid  = t >> 5;
    int kk = kptr[0] + 1;
    kk = kk < 1 ? 1 : (kk > 16 ? 16 : kk);

    __shared__ float smax[NCHUNK];
    __shared__ __align__(16) float aq[DD];
    __shared__ int   hist[HBINS];
    __shared__ float cand[CANDMAX];
    __shared__ int   clist[CLISTMAX];
    __shared__ float red[8];
    __shared__ int   ncc, n_cand, s_fb;
    __shared__ float s_thr, s_res;

    for (int c = t; c < NCHUNK; c += 256) smax[c] = g_gmaxT[(size_t)q * NCP + c];
    if (t < DD) aq[t] = __half2float(g_a[q * DD + t]);
    hist[t] = 0;
    if (t == 0) { ncc = 0; n_cand = 0; s_fb = 0; }
    __syncthreads();

    // ---- block max of chunk maxima ----
    float bm = -3.4e38f;
    for (int c = t; c < NCHUNK; c += 256) bm = fmaxf(bm, smax[c]);
    #pragma unroll
    for (int o = 16; o > 0; o >>= 1) bm = fmaxf(bm, __shfl_xor_sync(0xffffffffu, bm, o));
    if (lane == 0) red[wid] = bm;
    __syncthreads();
    float M = red[0];
    #pragma unroll
    for (int w = 1; w < 8; w++) M = fmaxf(M, red[w]);

    // ---- histogram of (M - v) over [0, HRANGE) ----
    const float invW = 1.0f / HW;
    for (int c = t; c < NCHUNK; c += 256) {
        float d = M - smax[c];
        int b = (int)(d * invW);
        if (b < 0) b = 0;
        if (b < HBINS) atomicAdd(&hist[b], 1);
    }
    __syncthreads();

    // ---- warp0: suffix scan -> first bin with cum >= kk ----
    if (t < 32) {
        int cnt[8], seg = 0;
        #pragma unroll
        for (int i = 0; i < 8; i++) { cnt[i] = hist[t * 8 + i]; seg += cnt[i]; }
        int inc = seg;
        #pragma unroll
        for (int o = 1; o < 32; o <<= 1) {
            int x = __shfl_up_sync(0xffffffffu, inc, o);
            if (lane >= o) inc += x;
        }
        int run = inc - seg;
        int bstar = 1 << 30;
        #pragma unroll
        for (int i = 0; i < 8; i++) {
            run += cnt[i];
            if (run >= kk && bstar == (1 << 30)) bstar = t * 8 + i;
        }
        #pragma unroll
        for (int o = 16; o > 0; o >>= 1) {
            int ob = __shfl_xor_sync(0xffffffffu, bstar, o);
            bstar = ob < bstar ? ob : bstar;
        }
        if (t == 0) {
            if (bstar >= HBINS) s_fb = 1;
            else s_thr = M - (float)(bstar + 1) * HW - EPS2;
        }
    }
    __syncthreads();

    bool fallback = (s_fb != 0);
    const float thr = s_thr;

    // ---- candidate chunk list ----
    if (!fallback) {
        for (int c = t; c < NCHUNK; c += 256) {
            if (smax[c] >= thr) {
                int p = atomicAdd(&ncc, 1);
                if (p < CLISTMAX) clist[p] = c;
            }
        }
        __syncthreads();
        if (ncc > CLISTMAX) fallback = true;
    }

    // ---- warp-cooperative recompute of candidate dots (coalesced 8B/lane rows) ----
    if (!fallback) {
        const int total = ncc * CHUNK;
        const float4 aqv = *(const float4*)&aq[lane * 4];
        for (int base = wid * 4; base < total; base += 32) {
            float d[4];
            #pragma unroll
            for (int u = 0; u < 4; u++) {
                int idx = base + u;
                bool ok = idx < total;
                int c   = ok ? clist[idx >> 5] : 0;
                int ref = c * CHUNK + (idx & 31);
                ok = ok && (ref < MREF);
                float dot = 0.0f;
                if (ok) {
                    uint2 raw = *((const uint2*)(g_b + (size_t)ref * DD) + lane);
                    float2 f0 = __half22float2(*(__half2*)&raw.x);
                    float2 f1 = __half22float2(*(__half2*)&raw.y);
                    dot = aqv.x * f0.x + aqv.y * f0.y + aqv.z * f1.x + aqv.w * f1.y;
                }
                d[u] = dot;
            }
            #pragma unroll
            for (int o = 16; o > 0; o >>= 1) {
                #pragma unroll
                for (int u = 0; u < 4; u++)
                    d[u] += __shfl_xor_sync(0xffffffffu, d[u], o);
            }
            if (lane < 4) {
                int idx = base + lane;
                if (idx < total) {
                    int c   = clist[idx >> 5];
                    int ref = c * CHUNK + (idx & 31);
                    if (ref < MREF && d[lane] >= thr) {
                        int p = atomicAdd(&n_cand, 1);
                        if (p < CANDMAX) cand[p] = d[lane];
                    }
                }
            }
        }
        __syncthreads();
        if (n_cand > CANDMAX || n_cand < kk) fallback = true;
    }

    int nc = n_cand;
    if (fallback) {
        // ---- exhaustive recompute, per-thread top-16 (always correct, rare) ----
        __syncthreads();
        float top[16];
        #pragma unroll
        for (int i = 0; i < 16; i++) top[i] = -3.4e38f;
        for (int ref = t; ref < MREF; ref += 256) {
            const __half2* b = (const __half2*)(g_b + (size_t)ref * DD);
            float dot = 0.0f;
            #pragma unroll
            for (int d = 0; d < 64; d++) {
                float2 bb = __half22float2(b[d]);
                dot += aq[2 * d] * bb.x + aq[2 * d + 1] * bb.y;
            }
            if (dot > top[15]) {
                top[15] = dot;
                #pragma unroll
                for (int i = 15; i > 0; i--) {
                    if (top[i] > top[i - 1]) { float tv = top[i-1]; top[i-1] = top[i]; top[i] = tv; }
                }
            }
        }
        __syncthreads();
        #pragma unroll
        for (int i = 0; i < 16; i++) cand[t * 16 + i] = top[i];
        __syncthreads();
        nc = CANDMAX;
    }

    // ---- warp0: exact kk-th largest via per-lane sorted lists + k-way shuffle merge ----
    if (t < 32) {
        float top[16];
        #pragma unroll
        for (int i = 0; i < 16; i++) top[i] = -3.4e38f;
        for (int c = t; c < nc; c += 32) {
            float v = cand[c];
            if (v > top[15]) {
                top[15] = v;
                #pragma unroll
                for (int i = 15; i > 0; i--) {
                    if (top[i] > top[i - 1]) { float tv = top[i-1]; top[i-1] = top[i]; top[i] = tv; }
                }
            }
        }
        float kth = -3.4e38f;
        for (int it = 0; it < kk; it++) {
            float v = top[0]; int bl = t;
            #pragma unroll
            for (int o = 16; o > 0; o >>= 1) {
                float ov = __shfl_xor_sync(0xffffffffu, v, o);
                int   ol = __shfl_xor_sync(0xffffffffu, bl, o);
                if (ov > v || (ov == v && ol < bl)) { v = ov; bl = ol; }
            }
            if (t == bl) {
                #pragma unroll
                for (int i = 0; i < 15; i++) top[i] = top[i + 1];
                top[15] = -3.4e38f;
            }
            kth = v;
        }
        if (t == 0) s_res = kth;
    }
    __syncthreads();

    if (t == 0) out[q] = sqrtf(fmaxf(2.0f - 2.0f * s_res, 1e-12f));
}

// ---------------- launch ----------------
extern "C" void kernel_launch(void* const* d_in, const int* in_sizes, int n_in,
                              void* d_out, int out_size) {
    const float* z    = (const float*)d_in[0];   // [2048,128]
    const float* ref  = (const float*)d_in[1];   // [50000,128]
    const int*   kptr = (const int*)d_in[2];     // scalar k
    float*       out  = (float*)d_out;           // [2048]

    const int smem_bytes = 2 * 128 * S * (int)sizeof(__half);   // 69632
    cudaFuncSetAttribute(knn_gemm, cudaFuncAttributeMaxDynamicSharedMemorySize, smem_bytes);

    normalize_rows<<<NQ / 8, 256>>>(z, NQ, 0);
    normalize_rows<<<(MREF + 7) / 8, 256>>>(ref, MREF, 1);

    dim3 grid(NTILES, 16);
    knn_gemm<<<grid, 256, smem_bytes>>>();

    phase2_select<<<NQ, 256>>>(kptr, out);
}